// round 15
// baseline (speedup 1.0000x reference)
#include <cuda_runtime.h>
#include <cuda_fp16.h>
#include <cstdint>

// ---------------- problem constants ----------------
constexpr int Mrows = 16384;          // B*C*T = 4*8*512
constexpr int K512  = 512;

// GEMM tiling (proven R8/R10/R12 geometry)
constexpr int BM = 128, BN = 256, BK = 32;
constexpr int KSTEPS = K512 / BK;     // 16

// smem rows padded to 40 halves = 80 B — ldmatrix conflict-free (proven)
constexpr int ROWB = 80;

// ---- gemm_q (QKV, fp32 convert-on-load) smem layout ----
constexpr int QA16   = 0;                        // fp16 A tile, single buffer
constexpr int A32ROW = 144;                      // fp32 staging row stride (16B-aligned, LDS-conflict-free)
constexpr int A32SZ  = 128 * A32ROW;             // 18432
constexpr int QSTG0  = BM * ROWB;                // 10240
constexpr int QB_OFF = 2 * A32SZ;                // 36864 (xr staging, xi staging, then B)
constexpr int QBH    = 0;                        // B hi within B region
constexpr int QBL    = BN * ROWB;                // 20480
constexpr int QSTAGE = QB_OFF + 2 * BN * ROWB;   // 77824
constexpr int SMEM_Q = QSTG0 + 2 * QSTAGE;       // 165888

// ---- gemm_o (fp16 direct, R12) smem layout ----
constexpr int ST_FA  = 0;
constexpr int ST_FBH = ST_FA + BM * ROWB;        // 10240
constexpr int ST_FBL = ST_FBH + BN * ROWB;       // 30720
constexpr int STAGE_F = ST_FBL + BN * ROWB;      // 51200
constexpr int SMEM_F = 2 * STAGE_F;              // 102400

constexpr size_t VS  = (size_t)Mrows * K512;
constexpr size_t WVS = (size_t)K512 * K512;

// ---------------- device scratch (allocation-free) ----------------
__device__ __half g_Ao[3][Mrows * K512];        // attention output fp16: r,i,s (o input)
__device__ __half g_Wf[4][6][K512 * K512];      // weights fp16 hi/lo x (r,i,s): q,k,v,o
__device__ float g_bR[4][K512];                 // br - bi
__device__ float g_bI[4][K512];                 // br + bi
__device__ float g_P[9][Mrows * K512];          // QKV products: layer*3 + p
__device__ float g_Po[3][Mrows * K512];         // o-layer products

// ---------------- PTX helpers (family-portable only) ----------------
#define CP_ASYNC16(dst, src) \
    asm volatile("cp.async.cg.shared.global [%0], [%1], 16;" :: "r"(dst), "l"(src))
#define CP_COMMIT() asm volatile("cp.async.commit_group;")
#define CP_WAIT(n)  asm volatile("cp.async.wait_group %0;" :: "n"(n))

#define LDSM_X4(r0, r1, r2, r3, addr) \
    asm volatile("ldmatrix.sync.aligned.m8n8.x4.shared.b16 {%0,%1,%2,%3}, [%4];" \
        : "=r"(r0), "=r"(r1), "=r"(r2), "=r"(r3) : "r"(addr))

__device__ __forceinline__ void mma_f16(float* d, const uint32_t* a, uint32_t b0, uint32_t b1) {
    asm volatile(
        "mma.sync.aligned.m16n8k16.row.col.f32.f16.f16.f32 "
        "{%0,%1,%2,%3}, {%4,%5,%6,%7}, {%8,%9}, {%0,%1,%2,%3};"
        : "+f"(d[0]), "+f"(d[1]), "+f"(d[2]), "+f"(d[3])
        : "r"(a[0]), "r"(a[1]), "r"(a[2]), "r"(a[3]), "r"(b0), "r"(b1));
}

// ============================================================================
// merged pack: 4 layers in one launch (grid.z = layer)
// Wr, Wi, Ws=Wr+Wi as fp16 hi/lo; biases br-bi, br+bi
// ============================================================================
struct PackArgs { const float *Wr[4], *Wi[4], *br[4], *bi[4]; };

__global__ void pack_f(PackArgs pa)
{
    const int layer = blockIdx.z;
    int idx = blockIdx.x * 256 + threadIdx.x;     // over 262144
    float vr = pa.Wr[layer][idx], vi = pa.Wi[layer][idx], vs = vr + vi;
    float vals[3] = {vr, vi, vs};
    __half* W6 = g_Wf[layer][0];
#pragma unroll
    for (int p = 0; p < 3; p++) {
        __half h = __float2half(vals[p]);
        W6[(size_t)(2 * p) * WVS + idx] = h;
        W6[(size_t)(2 * p + 1) * WVS + idx] = __float2half(vals[p] - __half2float(h));
    }
    if (idx < K512) {
        g_bR[layer][idx] = pa.br[layer][idx] - pa.bi[layer][idx];
        g_bI[layer][idx] = pa.br[layer][idx] + pa.bi[layer][idx];
    }
}

// ============================================================================
// gemm_q: QKV fp16x2 P-GEMM with fused fp32->fp16 convert-on-load.
// z = layer*3 + p;  A = fp32 xr (p=0), xi (p=1), xr+xi (p=2), converted in smem.
// P = A_fp16 @ (W_hi + W_lo)^T, fp32 accum.  512 threads, warp tile 32x64.
// ============================================================================
struct QArgs { const float *xr[3], *xi[3]; };

__global__ void __launch_bounds__(512, 1)
gemm_q(QArgs qa)
{
    const int z = blockIdx.z;
    const int layer = z / 3, p = z - 3 * layer;
    const float* A1 = (p == 1) ? qa.xi[layer] : qa.xr[layer];
    const float* A2 = qa.xi[layer];
    const bool dual = (p == 2);
    const __half* Bhi_g = g_Wf[layer][2 * p];
    const __half* Blo_g = g_Wf[layer][2 * p + 1];
    float* Pout = g_P[z];

    extern __shared__ char smem[];
    const int tid = threadIdx.x;
    const int wid = tid >> 5, lane = tid & 31;
    const int wm = wid >> 2, wn = wid & 3;        // 4 x 4 warps, tile 32 x 64
    const int r = lane >> 2, c = lane & 3;
    const int bm = blockIdx.x * BM, bn = blockIdx.y * BN;

    const uint32_t sb = (uint32_t)__cvta_generic_to_shared(smem);

    const int arow = (lane & 7) + ((lane >> 3) & 1) * 8;
    const int akof = ((lane >> 4) & 1) * 16;
    const uint32_t a_off = (uint32_t)((wm * 32 + arow) * ROWB + akof);
    const int brow = (lane & 7) + ((lane >> 4) & 1) * 8;
    const int bkof = ((lane >> 3) & 1) * 16;
    const uint32_t b_off = (uint32_t)((wn * 64 + brow) * ROWB + bkof);

    float acc[2][8][4];
#pragma unroll
    for (int mi = 0; mi < 2; mi++)
#pragma unroll
        for (int nj = 0; nj < 8; nj++)
#pragma unroll
            for (int e = 0; e < 4; e++) acc[mi][nj][e] = 0.f;

    // ---- loader: fp32 A into padded staging + fp16 B, all cp.async ----
    auto load_stage = [&](int s, int kt) {
        uint32_t base = sb + QSTG0 + s * QSTAGE;
#pragma unroll
        for (int i = 0; i < 2; i++) {             // A: 1024 16B chunks (4 fp32)
            int j = tid + i * 512;
            int row = j >> 3, ch = j & 7;
            size_t go = (size_t)(bm + row) * K512 + kt + ch * 4;
            CP_ASYNC16(base + row * A32ROW + ch * 16, A1 + go);
            if (dual)
                CP_ASYNC16(base + A32SZ + row * A32ROW + ch * 16, A2 + go);
        }
#pragma unroll
        for (int i = 0; i < 2; i++) {             // B: hi + lo
            int j = tid + i * 512;
            int row = j >> 2, ch = j & 3;
            size_t go = (size_t)(bn + row) * K512 + kt + ch * 8;
            CP_ASYNC16(base + QB_OFF + QBH + row * ROWB + ch * 16, Bhi_g + go);
            CP_ASYNC16(base + QB_OFF + QBL + row * ROWB + ch * 16, Blo_g + go);
        }
        CP_COMMIT();
    };

    // ---- conversion: staged fp32 -> fp16 A tile (single buffer at QA16) ----
    auto convert = [&](int s) {
        const char* st32 = smem + QSTG0 + s * QSTAGE;
        int row = tid >> 2, ch = tid & 3;         // 512 x 16B fp16 chunks
        const float4* p0 = (const float4*)(st32 + row * A32ROW + ch * 32);
        float4 u = p0[0], v = p0[1];
        if (dual) {
            const float4* p1 = (const float4*)(st32 + A32SZ + row * A32ROW + ch * 32);
            float4 w = p1[0], x = p1[1];
            u.x += w.x; u.y += w.y; u.z += w.z; u.w += w.w;
            v.x += x.x; v.y += x.y; v.z += x.z; v.w += x.w;
        }
        __half2 h0 = __floats2half2_rn(u.x, u.y), h1 = __floats2half2_rn(u.z, u.w);
        __half2 h2 = __floats2half2_rn(v.x, v.y), h3 = __floats2half2_rn(v.z, v.w);
        uint32_t d = sb + QA16 + row * ROWB + ch * 16;
        asm volatile("st.shared.v4.b32 [%0], {%1,%2,%3,%4};"
            :: "r"(d), "r"(*(uint32_t*)&h0), "r"(*(uint32_t*)&h1),
               "r"(*(uint32_t*)&h2), "r"(*(uint32_t*)&h3) : "memory");
    };

    load_stage(0, 0);

    for (int s = 0; s < KSTEPS; s++) {
        if (s + 1 < KSTEPS) {
            load_stage((s + 1) & 1, (s + 1) * BK);
            CP_WAIT(1);
        } else {
            CP_WAIT(0);
        }
        __syncthreads();
        convert(s & 1);
        __syncthreads();

        const uint32_t bbase = sb + QSTG0 + (s & 1) * QSTAGE + QB_OFF;
#pragma unroll
        for (int kk = 0; kk < 2; kk++) {
            const uint32_t ka = sb + QA16 + kk * 32;
            const uint32_t kb = bbase + kk * 32;
            uint32_t ah[2][4];
#pragma unroll
            for (int mi = 0; mi < 2; mi++)
                LDSM_X4(ah[mi][0], ah[mi][1], ah[mi][2], ah[mi][3],
                        ka + a_off + mi * (16 * ROWB));
#pragma unroll
            for (int g = 0; g < 4; g++) {
                uint32_t bh[4], bl[4];
                LDSM_X4(bh[0], bh[1], bh[2], bh[3], kb + QBH + b_off + g * (16 * ROWB));
                LDSM_X4(bl[0], bl[1], bl[2], bl[3], kb + QBL + b_off + g * (16 * ROWB));
#pragma unroll
                for (int mi = 0; mi < 2; mi++) {
                    mma_f16(acc[mi][2 * g + 0], ah[mi], bh[0], bh[1]);
                    mma_f16(acc[mi][2 * g + 0], ah[mi], bl[0], bl[1]);
                    mma_f16(acc[mi][2 * g + 1], ah[mi], bh[2], bh[3]);
                    mma_f16(acc[mi][2 * g + 1], ah[mi], bl[2], bl[3]);
                }
            }
        }
        __syncthreads();
    }

#pragma unroll
    for (int mi = 0; mi < 2; mi++)
#pragma unroll
        for (int nj = 0; nj < 8; nj++) {
            int ncol = bn + wn * 64 + nj * 8 + 2 * c;
            int row0 = bm + wm * 32 + mi * 16 + r;
#pragma unroll
            for (int hrow = 0; hrow < 2; hrow++) {
                float2 o = make_float2(acc[mi][nj][2 * hrow + 0], acc[mi][nj][2 * hrow + 1]);
                *(float2*)&Pout[(size_t)(row0 + 8 * hrow) * K512 + ncol] = o;
            }
        }
}

// ============================================================================
// gemm_o: o-layer fp16x2 P-GEMM (R12 path, fp16 A from g_Ao).  z = p.
// ============================================================================
__global__ void __launch_bounds__(512, 1)
gemm_o(void)
{
    const int z = blockIdx.z;
    const __half* Ah_g  = g_Ao[z];
    const __half* Bhi_g = g_Wf[3][2 * z];
    const __half* Blo_g = g_Wf[3][2 * z + 1];
    float* Pout = g_Po[z];

    extern __shared__ char smem[];
    const int tid = threadIdx.x;
    const int wid = tid >> 5, lane = tid & 31;
    const int wm = wid >> 2, wn = wid & 3;
    const int r = lane >> 2, c = lane & 3;
    const int bm = blockIdx.x * BM, bn = blockIdx.y * BN;

    const uint32_t sb = (uint32_t)__cvta_generic_to_shared(smem);

    const int arow = (lane & 7) + ((lane >> 3) & 1) * 8;
    const int akof = ((lane >> 4) & 1) * 16;
    const uint32_t a_off = (uint32_t)((wm * 32 + arow) * ROWB + akof);
    const int brow = (lane & 7) + ((lane >> 4) & 1) * 8;
    const int bkof = ((lane >> 3) & 1) * 16;
    const uint32_t b_off = (uint32_t)((wn * 64 + brow) * ROWB + bkof);

    float acc[2][8][4];
#pragma unroll
    for (int mi = 0; mi < 2; mi++)
#pragma unroll
        for (int nj = 0; nj < 8; nj++)
#pragma unroll
            for (int e = 0; e < 4; e++) acc[mi][nj][e] = 0.f;

    auto load_stage = [&](int s, int kt) {
        uint32_t base = sb + s * STAGE_F;
        {
            int row = tid >> 2, ch = tid & 3;
            CP_ASYNC16(base + ST_FA + row * ROWB + ch * 16,
                       Ah_g + (size_t)(bm + row) * K512 + kt + ch * 8);
        }
#pragma unroll
        for (int i = 0; i < 2; i++) {
            int j = tid + i * 512;
            int row = j >> 2, ch = j & 3;
            size_t go = (size_t)(bn + row) * K512 + kt + ch * 8;
            CP_ASYNC16(base + ST_FBH + row * ROWB + ch * 16, Bhi_g + go);
            CP_ASYNC16(base + ST_FBL + row * ROWB + ch * 16, Blo_g + go);
        }
        CP_COMMIT();
    };

    load_stage(0, 0);

    for (int s = 0; s < KSTEPS; s++) {
        if (s + 1 < KSTEPS) {
            load_stage((s + 1) & 1, (s + 1) * BK);
            CP_WAIT(1);
        } else {
            CP_WAIT(0);
        }
        __syncthreads();

        const uint32_t stb = sb + (s & 1) * STAGE_F;
#pragma unroll
        for (int kk = 0; kk < 2; kk++) {
            const uint32_t kb = stb + kk * 32;
            uint32_t ah[2][4];
#pragma unroll
            for (int mi = 0; mi < 2; mi++)
                LDSM_X4(ah[mi][0], ah[mi][1], ah[mi][2], ah[mi][3],
                        kb + ST_FA + a_off + mi * (16 * ROWB));
#pragma unroll
            for (int g = 0; g < 4; g++) {
                uint32_t bh[4], bl[4];
                LDSM_X4(bh[0], bh[1], bh[2], bh[3], kb + ST_FBH + b_off + g * (16 * ROWB));
                LDSM_X4(bl[0], bl[1], bl[2], bl[3], kb + ST_FBL + b_off + g * (16 * ROWB));
#pragma unroll
                for (int mi = 0; mi < 2; mi++) {
                    mma_f16(acc[mi][2 * g + 0], ah[mi], bh[0], bh[1]);
                    mma_f16(acc[mi][2 * g + 0], ah[mi], bl[0], bl[1]);
                    mma_f16(acc[mi][2 * g + 1], ah[mi], bh[2], bh[3]);
                    mma_f16(acc[mi][2 * g + 1], ah[mi], bl[2], bl[3]);
                }
            }
        }
        __syncthreads();
    }

#pragma unroll
    for (int mi = 0; mi < 2; mi++)
#pragma unroll
        for (int nj = 0; nj < 8; nj++) {
            int ncol = bn + wn * 64 + nj * 8 + 2 * c;
            int row0 = bm + wm * 32 + mi * 16 + r;
#pragma unroll
            for (int hrow = 0; hrow < 2; hrow++) {
                float2 o = make_float2(acc[mi][nj][2 * hrow + 0], acc[mi][nj][2 * hrow + 1]);
                *(float2*)&Pout[(size_t)(row0 + 8 * hrow) * K512 + ncol] = o;
            }
        }
}

// ============================================================================
// channel attention with fused Gauss combine of Q/K/V (reads g_P fp32),
// writes o-GEMM input splits g_Ao (fp16 r,i,s)
// ============================================================================
__global__ void attn_kernel()
{
    __shared__ float sm[6][8][68];
    __shared__ float ssr[8][9], ssi[8][9];

    const int t = blockIdx.x, h = blockIdx.y, b = blockIdx.z;
    const int tid = threadIdx.x;

    {
        int cch = tid >> 4, d4 = (tid & 15) << 2;
        size_t m = ((size_t)(b * 8 + cch) * 512 + t);
        size_t off = m * K512 + h * 64 + d4;
        int col = h * 64 + d4;

#pragma unroll
        for (int layer = 0; layer < 3; layer++) {
            float4 p1 = *(const float4*)&g_P[layer * 3 + 0][off];
            float4 p2 = *(const float4*)&g_P[layer * 3 + 1][off];
            float4 p3 = *(const float4*)&g_P[layer * 3 + 2][off];
            float4 br = *(const float4*)&g_bR[layer][col];
            float4 bi = *(const float4*)&g_bI[layer][col];
            float4 yr, yi;
            yr.x = p1.x - p2.x + br.x;  yi.x = p3.x - p1.x - p2.x + bi.x;
            yr.y = p1.y - p2.y + br.y;  yi.y = p3.y - p1.y - p2.y + bi.y;
            yr.z = p1.z - p2.z + br.z;  yi.z = p3.z - p1.z - p2.z + bi.z;
            yr.w = p1.w - p2.w + br.w;  yi.w = p3.w - p1.w - p2.w + bi.w;
            if (layer == 2) {
                yr.x = yr.x >= 0.f ? yr.x : 0.01f * yr.x;
                yr.y = yr.y >= 0.f ? yr.y : 0.01f * yr.y;
                yr.z = yr.z >= 0.f ? yr.z : 0.01f * yr.z;
                yr.w = yr.w >= 0.f ? yr.w : 0.01f * yr.w;
                yi.x = yi.x >= 0.f ? yi.x : 0.01f * yi.x;
                yi.y = yi.y >= 0.f ? yi.y : 0.01f * yi.y;
                yi.z = yi.z >= 0.f ? yi.z : 0.01f * yi.z;
                yi.w = yi.w >= 0.f ? yi.w : 0.01f * yi.w;
            }
            *(float4*)&sm[2 * layer + 0][cch][d4] = yr;
            *(float4*)&sm[2 * layer + 1][cch][d4] = yi;
        }
    }
    __syncthreads();

    if (tid < 64) {
        int cc = tid >> 3, e = tid & 7;
        float ar = 0.f, ai = 0.f;
#pragma unroll 8
        for (int d = 0; d < 64; d++) {
            float qr = sm[0][cc][d], qi = sm[1][cc][d];
            float kr = sm[2][e][d],  ki = sm[3][e][d];
            ar = fmaf(qr, kr, fmaf(qi, ki, ar));
            ai = fmaf(qr, ki, fmaf(-qi, kr, ai));
        }
        ssr[cc][e] = ar * 0.125f;
        ssi[cc][e] = ai * 0.125f;
    }
    __syncthreads();

#pragma unroll
    for (int i = 0; i < 4; i++) {
        int idx = tid + i * 128;
        int cc = idx >> 6, d = idx & 63;
        float xr = 0.f, xi = 0.f;
#pragma unroll
        for (int e = 0; e < 8; e++) {
            float sr_ = ssr[cc][e], si_ = ssi[cc][e];
            float vr = sm[4][e][d], vi = sm[5][e][d];
            xr = fmaf(sr_, vr, fmaf(-si_, vi, xr));
            xi = fmaf(si_, vr, fmaf(sr_, vi, xi));
        }
        xr = xr >= 0.f ? xr : 0.01f * xr;
        xi = xi >= 0.f ? xi : 0.01f * xi;
        size_t mrow = (size_t)(b * 8 + cc) * 512 + t;
        size_t o = mrow * K512 + h * 64 + d;
        g_Ao[0][o] = __float2half(xr);
        g_Ao[1][o] = __float2half(xi);
        g_Ao[2][o] = __float2half(xr + xi);
    }
}

// ============================================================================
// o-layer Gauss combine: d_out = [Yr | Yi] from g_Po + biases
// ============================================================================
__global__ void combine_out(float* __restrict__ out)
{
    size_t i4 = (size_t)(blockIdx.x * 256 + threadIdx.x) * 4;
    int col = (int)(i4 & 511);
    float4 p1 = *(const float4*)&g_Po[0][i4];
    float4 p2 = *(const float4*)&g_Po[1][i4];
    float4 p3 = *(const float4*)&g_Po[2][i4];
    float4 br = *(const float4*)&g_bR[3][col];
    float4 bi = *(const float4*)&g_bI[3][col];
    float4 yr, yi;
    yr.x = p1.x - p2.x + br.x;  yi.x = p3.x - p1.x - p2.x + bi.x;
    yr.y = p1.y - p2.y + br.y;  yi.y = p3.y - p1.y - p2.y + bi.y;
    yr.z = p1.z - p2.z + br.z;  yi.z = p3.z - p1.z - p2.z + bi.z;
    yr.w = p1.w - p2.w + br.w;  yi.w = p3.w - p1.w - p2.w + bi.w;
    *(float4*)&out[i4] = yr;
    *(float4*)&out[(size_t)Mrows * K512 + i4] = yi;
}

// ============================================================================
// host side: pack(merged), gemm_q(QKV, fused split), attn, gemm_o, combine
// ============================================================================
extern "C" void kernel_launch(void* const* d_in, const int* in_sizes, int n_in,
                              void* d_out, int out_size)
{
    const float* in[22];
    for (int i = 0; i < 22; i++) in[i] = (const float*)d_in[i];

    cudaFuncSetAttribute(gemm_q, cudaFuncAttributeMaxDynamicSharedMemorySize, SMEM_Q);
    cudaFuncSetAttribute(gemm_o, cudaFuncAttributeMaxDynamicSharedMemorySize, SMEM_F);

    // weights: 6=Wq_r 7=bq_r 8=Wq_i 9=bq_i | 10..13 k | 14..17 v | 18..21 o
    PackArgs pa;
    for (int l = 0; l < 4; l++) {
        pa.Wr[l] = in[6 + 4 * l];
        pa.br[l] = in[7 + 4 * l];
        pa.Wi[l] = in[8 + 4 * l];
        pa.bi[l] = in[9 + 4 * l];
    }
    pack_f<<<dim3(1024, 1, 4), 256>>>(pa);

    // 9 QKV P-GEMMs with fused fp32->fp16 conversion (no split kernel)
    QArgs qa;
    qa.xr[0] = in[0]; qa.xi[0] = in[1];
    qa.xr[1] = in[2]; qa.xi[1] = in[3];
    qa.xr[2] = in[4]; qa.xi[2] = in[5];
    gemm_q<<<dim3(Mrows / BM, K512 / BN, 9), 512, SMEM_Q>>>(qa);

    // attention (fused QKV Gauss combine)
    attn_kernel<<<dim3(512, 8, 4), 128>>>();

    // 3 o-layer P-GEMMs, then combine into d_out
    gemm_o<<<dim3(Mrows / BM, K512 / BN, 3), 512, SMEM_F>>>();
    combine_out<<<8192, 256>>>((float*)d_out);
}

// round 16
// speedup vs baseline: 1.0797x; 1.0797x over previous
#include <cuda_runtime.h>
#include <cuda_fp16.h>
#include <cstdint>

// ---------------- problem constants ----------------
constexpr int Mrows = 16384;          // B*C*T = 4*8*512
constexpr int K512  = 512;

// GEMM tiling (proven R8/R10/R12 geometry)
constexpr int BM = 128, BN = 256, BK = 32;
constexpr int KSTEPS = K512 / BK;     // 16
constexpr int NSTG = 3;               // pipeline depth (was 2)

// smem rows padded to 40 halves = 80 B — ldmatrix conflict-free (proven)
constexpr int ROWB = 80;

// fp16x2 stage: A (single), Bhi, Blo
constexpr int ST_FA  = 0;
constexpr int ST_FBH = ST_FA + BM * ROWB;       // 10240
constexpr int ST_FBL = ST_FBH + BN * ROWB;      // 30720
constexpr int STAGE_F = ST_FBL + BN * ROWB;     // 51200
constexpr int SMEM_F = NSTG * STAGE_F;          // 153600

constexpr size_t VS  = (size_t)Mrows * K512;    // activation variant stride
constexpr size_t WVS = (size_t)K512 * K512;     // weight variant stride

// ---------------- device scratch (allocation-free) ----------------
__device__ __half g_Xh[3][3][Mrows * K512];     // q,k,v activations fp16: r,i,s
__device__ __half g_Ao[3][Mrows * K512];        // attention output fp16: r,i,s (o input)
__device__ __half g_Wf[4][6][K512 * K512];      // weights fp16 hi/lo x (r,i,s): q,k,v,o
__device__ float g_bR[4][K512];                 // br - bi
__device__ float g_bI[4][K512];                 // br + bi
__device__ float g_P[9][Mrows * K512];          // QKV products: layer*3 + p
__device__ float g_Po[3][Mrows * K512];         // o-layer products

// ---------------- PTX helpers (family-portable only) ----------------
#define CP_ASYNC16(dst, src) \
    asm volatile("cp.async.cg.shared.global [%0], [%1], 16;" :: "r"(dst), "l"(src))
#define CP_COMMIT() asm volatile("cp.async.commit_group;")
#define CP_WAIT(n)  asm volatile("cp.async.wait_group %0;" :: "n"(n))

#define LDSM_X4(r0, r1, r2, r3, addr) \
    asm volatile("ldmatrix.sync.aligned.m8n8.x4.shared.b16 {%0,%1,%2,%3}, [%4];" \
        : "=r"(r0), "=r"(r1), "=r"(r2), "=r"(r3) : "r"(addr))

__device__ __forceinline__ void mma_f16(float* d, const uint32_t* a, uint32_t b0, uint32_t b1) {
    asm volatile(
        "mma.sync.aligned.m16n8k16.row.col.f32.f16.f16.f32 "
        "{%0,%1,%2,%3}, {%4,%5,%6,%7}, {%8,%9}, {%0,%1,%2,%3};"
        : "+f"(d[0]), "+f"(d[1]), "+f"(d[2]), "+f"(d[3])
        : "r"(a[0]), "r"(a[1]), "r"(a[2]), "r"(a[3]), "r"(b0), "r"(b1));
}

// ============================================================================
// merged pack: 4 layers in one launch (grid.z = layer)
// Wr, Wi, Ws=Wr+Wi as fp16 hi/lo; biases br-bi, br+bi
// ============================================================================
struct PackArgs { const float *Wr[4], *Wi[4], *br[4], *bi[4]; };

__global__ void pack_f(PackArgs pa)
{
    const int layer = blockIdx.z;
    int idx = blockIdx.x * 256 + threadIdx.x;     // over 262144
    float vr = pa.Wr[layer][idx], vi = pa.Wi[layer][idx], vs = vr + vi;
    float vals[3] = {vr, vi, vs};
    __half* W6 = g_Wf[layer][0];
#pragma unroll
    for (int p = 0; p < 3; p++) {
        __half h = __float2half(vals[p]);
        W6[(size_t)(2 * p) * WVS + idx] = h;
        W6[(size_t)(2 * p + 1) * WVS + idx] = __float2half(vals[p] - __half2float(h));
    }
    if (idx < K512) {
        g_bR[layer][idx] = pa.br[layer][idx] - pa.bi[layer][idx];
        g_bI[layer][idx] = pa.br[layer][idx] + pa.bi[layer][idx];
    }
}

// ============================================================================
// merged split: 3 tensors in one launch (grid.z = q/k/v)
// fp32 (xr, xi) -> single fp16 r, i, s=r+i
// ============================================================================
struct alignas(8) HF4 { __half v[4]; };
struct SplitArgs { const float *xr[3], *xi[3]; };

__global__ void split_f(SplitArgs sa)
{
    const int z = blockIdx.z;
    size_t i4 = (size_t)(blockIdx.x * 256 + threadIdx.x) * 4;
    float4 vr = *(const float4*)(sa.xr[z] + i4);
    float4 vi = *(const float4*)(sa.xi[z] + i4);
    float ar[4] = {vr.x, vr.y, vr.z, vr.w};
    float ai[4] = {vi.x, vi.y, vi.z, vi.w};
    HF4 out[3];
#pragma unroll
    for (int j = 0; j < 4; j++) {
        out[0].v[j] = __float2half(ar[j]);
        out[1].v[j] = __float2half(ai[j]);
        out[2].v[j] = __float2half(ar[j] + ai[j]);
    }
    __half* X = g_Xh[z][0];
#pragma unroll
    for (int v = 0; v < 3; v++)
        *(HF4*)(X + (size_t)v * VS + i4) = out[v];
}

// ============================================================================
// fp16x2 P-GEMM: P = A_v @ (W_hi + W_lo)^T
// mode 0: QKV (z = layer*3 + p), mode 1: o-layer (z = p)
// 3-stage cp.async ring, ONE __syncthreads per stage, loads for s+2 issued
// before compute of s.  BM=128 BN=256 BK=32, 512 threads, warp tile 32x64.
// ============================================================================
__global__ void __launch_bounds__(512, 1)
gemm_f(int mode)
{
    const int z = blockIdx.z;
    const __half *Ah_g, *Bhi_g, *Blo_g;
    float* Pout;
    if (mode == 0) {
        int layer = z / 3, p = z - 3 * layer;
        Ah_g  = g_Xh[layer][p];
        Bhi_g = g_Wf[layer][2 * p];
        Blo_g = g_Wf[layer][2 * p + 1];
        Pout  = g_P[z];
    } else {
        Ah_g  = g_Ao[z];
        Bhi_g = g_Wf[3][2 * z];
        Blo_g = g_Wf[3][2 * z + 1];
        Pout  = g_Po[z];
    }

    extern __shared__ char smem[];
    const int tid = threadIdx.x;
    const int wid = tid >> 5, lane = tid & 31;
    const int wm = wid >> 2, wn = wid & 3;        // 4 x 4 warps, tile 32 x 64
    const int r = lane >> 2, c = lane & 3;
    const int bm = blockIdx.x * BM, bn = blockIdx.y * BN;

    const uint32_t sb = (uint32_t)__cvta_generic_to_shared(smem);

    const int arow = (lane & 7) + ((lane >> 3) & 1) * 8;
    const int akof = ((lane >> 4) & 1) * 16;
    const uint32_t a_off = (uint32_t)((wm * 32 + arow) * ROWB + akof);
    const int brow = (lane & 7) + ((lane >> 4) & 1) * 8;
    const int bkof = ((lane >> 3) & 1) * 16;
    const uint32_t b_off = (uint32_t)((wn * 64 + brow) * ROWB + bkof);

    float acc[2][8][4];
#pragma unroll
    for (int mi = 0; mi < 2; mi++)
#pragma unroll
        for (int nj = 0; nj < 8; nj++)
#pragma unroll
            for (int e = 0; e < 4; e++) acc[mi][nj][e] = 0.f;

    // precomputed per-thread load indices
    const int a_row = tid >> 2, a_ch = tid & 3;

    auto load_stage = [&](int slot, int kt) {
        uint32_t base = sb + slot * STAGE_F;
        CP_ASYNC16(base + ST_FA + a_row * ROWB + a_ch * 16,
                   Ah_g + (size_t)(bm + a_row) * K512 + kt + a_ch * 8);
#pragma unroll
        for (int i = 0; i < 2; i++) {
            int j = tid + i * 512;
            int row = j >> 2, ch = j & 3;
            size_t go = (size_t)(bn + row) * K512 + kt + ch * 8;
            CP_ASYNC16(base + ST_FBH + row * ROWB + ch * 16, Bhi_g + go);
            CP_ASYNC16(base + ST_FBL + row * ROWB + ch * 16, Blo_g + go);
        }
        CP_COMMIT();
    };

    // prologue: stages 0 and 1 in flight
    load_stage(0, 0);
    load_stage(1, BK);

    int slot = 0, next_slot = 2;
    for (int s = 0; s < KSTEPS; s++) {
        CP_WAIT(1);               // stage s complete (s+1 still in flight)
        __syncthreads();          // smem visibility + fences reuse of slot (s-1)

        if (s + 2 < KSTEPS) {
            load_stage(next_slot, (s + 2) * BK);
        }

        const uint32_t stb = sb + slot * STAGE_F;
#pragma unroll
        for (int kk = 0; kk < 2; kk++) {
            const uint32_t kb = stb + kk * 32;
            uint32_t ah[2][4];
#pragma unroll
            for (int mi = 0; mi < 2; mi++)
                LDSM_X4(ah[mi][0], ah[mi][1], ah[mi][2], ah[mi][3],
                        kb + ST_FA + a_off + mi * (16 * ROWB));
#pragma unroll
            for (int g = 0; g < 4; g++) {
                uint32_t bh[4], bl[4];
                LDSM_X4(bh[0], bh[1], bh[2], bh[3], kb + ST_FBH + b_off + g * (16 * ROWB));
                LDSM_X4(bl[0], bl[1], bl[2], bl[3], kb + ST_FBL + b_off + g * (16 * ROWB));
#pragma unroll
                for (int mi = 0; mi < 2; mi++) {
                    mma_f16(acc[mi][2 * g + 0], ah[mi], bh[0], bh[1]);
                    mma_f16(acc[mi][2 * g + 0], ah[mi], bl[0], bl[1]);
                    mma_f16(acc[mi][2 * g + 1], ah[mi], bh[2], bh[3]);
                    mma_f16(acc[mi][2 * g + 1], ah[mi], bl[2], bl[3]);
                }
            }
        }

        slot = (slot == NSTG - 1) ? 0 : slot + 1;
        next_slot = (next_slot == NSTG - 1) ? 0 : next_slot + 1;
    }

#pragma unroll
    for (int mi = 0; mi < 2; mi++)
#pragma unroll
        for (int nj = 0; nj < 8; nj++) {
            int ncol = bn + wn * 64 + nj * 8 + 2 * c;
            int row0 = bm + wm * 32 + mi * 16 + r;
#pragma unroll
            for (int hrow = 0; hrow < 2; hrow++) {
                float2 o = make_float2(acc[mi][nj][2 * hrow + 0], acc[mi][nj][2 * hrow + 1]);
                *(float2*)&Pout[(size_t)(row0 + 8 * hrow) * K512 + ncol] = o;
            }
        }
}

// ============================================================================
// channel attention with fused Gauss combine of Q/K/V (reads g_P fp32),
// writes o-GEMM input splits g_Ao (fp16 r,i,s)
// ============================================================================
__global__ void attn_kernel()
{
    __shared__ float sm[6][8][68];
    __shared__ float ssr[8][9], ssi[8][9];

    const int t = blockIdx.x, h = blockIdx.y, b = blockIdx.z;
    const int tid = threadIdx.x;

    {
        int cch = tid >> 4, d4 = (tid & 15) << 2;
        size_t m = ((size_t)(b * 8 + cch) * 512 + t);
        size_t off = m * K512 + h * 64 + d4;
        int col = h * 64 + d4;

#pragma unroll
        for (int layer = 0; layer < 3; layer++) {
            float4 p1 = *(const float4*)&g_P[layer * 3 + 0][off];
            float4 p2 = *(const float4*)&g_P[layer * 3 + 1][off];
            float4 p3 = *(const float4*)&g_P[layer * 3 + 2][off];
            float4 br = *(const float4*)&g_bR[layer][col];
            float4 bi = *(const float4*)&g_bI[layer][col];
            float4 yr, yi;
            yr.x = p1.x - p2.x + br.x;  yi.x = p3.x - p1.x - p2.x + bi.x;
            yr.y = p1.y - p2.y + br.y;  yi.y = p3.y - p1.y - p2.y + bi.y;
            yr.z = p1.z - p2.z + br.z;  yi.z = p3.z - p1.z - p2.z + bi.z;
            yr.w = p1.w - p2.w + br.w;  yi.w = p3.w - p1.w - p2.w + bi.w;
            if (layer == 2) {
                yr.x = yr.x >= 0.f ? yr.x : 0.01f * yr.x;
                yr.y = yr.y >= 0.f ? yr.y : 0.01f * yr.y;
                yr.z = yr.z >= 0.f ? yr.z : 0.01f * yr.z;
                yr.w = yr.w >= 0.f ? yr.w : 0.01f * yr.w;
                yi.x = yi.x >= 0.f ? yi.x : 0.01f * yi.x;
                yi.y = yi.y >= 0.f ? yi.y : 0.01f * yi.y;
                yi.z = yi.z >= 0.f ? yi.z : 0.01f * yi.z;
                yi.w = yi.w >= 0.f ? yi.w : 0.01f * yi.w;
            }
            *(float4*)&sm[2 * layer + 0][cch][d4] = yr;
            *(float4*)&sm[2 * layer + 1][cch][d4] = yi;
        }
    }
    __syncthreads();

    if (tid < 64) {
        int cc = tid >> 3, e = tid & 7;
        float ar = 0.f, ai = 0.f;
#pragma unroll 8
        for (int d = 0; d < 64; d++) {
            float qr = sm[0][cc][d], qi = sm[1][cc][d];
            float kr = sm[2][e][d],  ki = sm[3][e][d];
            ar = fmaf(qr, kr, fmaf(qi, ki, ar));
            ai = fmaf(qr, ki, fmaf(-qi, kr, ai));
        }
        ssr[cc][e] = ar * 0.125f;
        ssi[cc][e] = ai * 0.125f;
    }
    __syncthreads();

#pragma unroll
    for (int i = 0; i < 4; i++) {
        int idx = tid + i * 128;
        int cc = idx >> 6, d = idx & 63;
        float xr = 0.f, xi = 0.f;
#pragma unroll
        for (int e = 0; e < 8; e++) {
            float sr_ = ssr[cc][e], si_ = ssi[cc][e];
            float vr = sm[4][e][d], vi = sm[5][e][d];
            xr = fmaf(sr_, vr, fmaf(-si_, vi, xr));
            xi = fmaf(si_, vr, fmaf(sr_, vi, xi));
        }
        xr = xr >= 0.f ? xr : 0.01f * xr;
        xi = xi >= 0.f ? xi : 0.01f * xi;
        size_t mrow = (size_t)(b * 8 + cc) * 512 + t;
        size_t o = mrow * K512 + h * 64 + d;
        g_Ao[0][o] = __float2half(xr);
        g_Ao[1][o] = __float2half(xi);
        g_Ao[2][o] = __float2half(xr + xi);
    }
}

// ============================================================================
// o-layer Gauss combine: d_out = [Yr | Yi] from g_Po + biases
// ============================================================================
__global__ void combine_out(float* __restrict__ out)
{
    size_t i4 = (size_t)(blockIdx.x * 256 + threadIdx.x) * 4;
    int col = (int)(i4 & 511);
    float4 p1 = *(const float4*)&g_Po[0][i4];
    float4 p2 = *(const float4*)&g_Po[1][i4];
    float4 p3 = *(const float4*)&g_Po[2][i4];
    float4 br = *(const float4*)&g_bR[3][col];
    float4 bi = *(const float4*)&g_bI[3][col];
    float4 yr, yi;
    yr.x = p1.x - p2.x + br.x;  yi.x = p3.x - p1.x - p2.x + bi.x;
    yr.y = p1.y - p2.y + br.y;  yi.y = p3.y - p1.y - p2.y + bi.y;
    yr.z = p1.z - p2.z + br.z;  yi.z = p3.z - p1.z - p2.z + bi.z;
    yr.w = p1.w - p2.w + br.w;  yi.w = p3.w - p1.w - p2.w + bi.w;
    *(float4*)&out[i4] = yr;
    *(float4*)&out[(size_t)Mrows * K512 + i4] = yi;
}

// ============================================================================
// host side
// ============================================================================
extern "C" void kernel_launch(void* const* d_in, const int* in_sizes, int n_in,
                              void* d_out, int out_size)
{
    const float* in[22];
    for (int i = 0; i < 22; i++) in[i] = (const float*)d_in[i];

    cudaFuncSetAttribute(gemm_f, cudaFuncAttributeMaxDynamicSharedMemorySize, SMEM_F);

    // weights: 6=Wq_r 7=bq_r 8=Wq_i 9=bq_i | 10..13 k | 14..17 v | 18..21 o
    PackArgs pa;
    for (int l = 0; l < 4; l++) {
        pa.Wr[l] = in[6 + 4 * l];
        pa.br[l] = in[7 + 4 * l];
        pa.Wi[l] = in[8 + 4 * l];
        pa.bi[l] = in[9 + 4 * l];
    }
    pack_f<<<dim3(1024, 1, 4), 256>>>(pa);

    // input splits (q, k, v) -> fp16 r,i,s (merged launch)
    SplitArgs sa;
    sa.xr[0] = in[0]; sa.xi[0] = in[1];
    sa.xr[1] = in[2]; sa.xi[1] = in[3];
    sa.xr[2] = in[4]; sa.xi[2] = in[5];
    split_f<<<dim3(8192, 1, 3), 256>>>(sa);

    // 9 QKV P-GEMMs (fp16x2) in one launch
    gemm_f<<<dim3(Mrows / BM, K512 / BN, 9), 512, SMEM_F>>>(0);

    // attention (fused QKV Gauss combine)
    attn_kernel<<<dim3(512, 8, 4), 128>>>();

    // 3 o-layer P-GEMMs (fp16x2), then combine into d_out
    gemm_f<<<dim3(Mrows / BM, K512 / BN, 3), 512, SMEM_F>>>(1);
    combine_out<<<8192, 256>>>((float*)d_out);
}

// round 17
// speedup vs baseline: 1.1484x; 1.0637x over previous
#include <cuda_runtime.h>
#include <cuda_fp16.h>
#include <cstdint>

// ---------------- problem constants ----------------
constexpr int Mrows = 16384;          // B*C*T = 4*8*512
constexpr int K512  = 512;

// GEMM tiling: 256 threads, 2 CTAs/SM (register-balanced)
constexpr int BM = 128, BN = 128, BK = 32;
constexpr int KSTEPS = K512 / BK;     // 16
constexpr int NSTG = 3;               // cp.async ring depth

// smem rows padded to 40 halves = 80 B — ldmatrix conflict-free (proven)
constexpr int ROWB = 80;

// fp16x2 stage: A (single), Bhi, Blo — all 128-row tiles
constexpr int ST_FA  = 0;
constexpr int ST_FBH = ST_FA + BM * ROWB;       // 10240
constexpr int ST_FBL = ST_FBH + BN * ROWB;      // 20480
constexpr int STAGE_F = ST_FBL + BN * ROWB;     // 30720
constexpr int SMEM_F = NSTG * STAGE_F;          // 92160  (x2 CTAs = 184320)

constexpr size_t VS  = (size_t)Mrows * K512;    // activation variant stride
constexpr size_t WVS = (size_t)K512 * K512;     // weight variant stride

// ---------------- device scratch (allocation-free) ----------------
__device__ __half g_Xh[3][3][Mrows * K512];     // q,k,v activations fp16: r,i,s
__device__ __half g_Ao[3][Mrows * K512];        // attention output fp16: r,i,s (o input)
__device__ __half g_Wf[4][6][K512 * K512];      // weights fp16 hi/lo x (r,i,s): q,k,v,o
__device__ float g_bR[4][K512];                 // br - bi
__device__ float g_bI[4][K512];                 // br + bi
__device__ float g_P[9][Mrows * K512];          // QKV products: layer*3 + p
__device__ float g_Po[3][Mrows * K512];         // o-layer products

// ---------------- PTX helpers (family-portable only) ----------------
#define CP_ASYNC16(dst, src) \
    asm volatile("cp.async.cg.shared.global [%0], [%1], 16;" :: "r"(dst), "l"(src))
#define CP_COMMIT() asm volatile("cp.async.commit_group;")
#define CP_WAIT(n)  asm volatile("cp.async.wait_group %0;" :: "n"(n))

#define LDSM_X4(r0, r1, r2, r3, addr) \
    asm volatile("ldmatrix.sync.aligned.m8n8.x4.shared.b16 {%0,%1,%2,%3}, [%4];" \
        : "=r"(r0), "=r"(r1), "=r"(r2), "=r"(r3) : "r"(addr))

__device__ __forceinline__ void mma_f16(float* d, const uint32_t* a, uint32_t b0, uint32_t b1) {
    asm volatile(
        "mma.sync.aligned.m16n8k16.row.col.f32.f16.f16.f32 "
        "{%0,%1,%2,%3}, {%4,%5,%6,%7}, {%8,%9}, {%0,%1,%2,%3};"
        : "+f"(d[0]), "+f"(d[1]), "+f"(d[2]), "+f"(d[3])
        : "r"(a[0]), "r"(a[1]), "r"(a[2]), "r"(a[3]), "r"(b0), "r"(b1));
}

// ============================================================================
// merged pack: 4 layers in one launch (grid.z = layer)
// Wr, Wi, Ws=Wr+Wi as fp16 hi/lo; biases br-bi, br+bi
// ============================================================================
struct PackArgs { const float *Wr[4], *Wi[4], *br[4], *bi[4]; };

__global__ void pack_f(PackArgs pa)
{
    const int layer = blockIdx.z;
    int idx = blockIdx.x * 256 + threadIdx.x;     // over 262144
    float vr = pa.Wr[layer][idx], vi = pa.Wi[layer][idx], vs = vr + vi;
    float vals[3] = {vr, vi, vs};
    __half* W6 = g_Wf[layer][0];
#pragma unroll
    for (int p = 0; p < 3; p++) {
        __half h = __float2half(vals[p]);
        W6[(size_t)(2 * p) * WVS + idx] = h;
        W6[(size_t)(2 * p + 1) * WVS + idx] = __float2half(vals[p] - __half2float(h));
    }
    if (idx < K512) {
        g_bR[layer][idx] = pa.br[layer][idx] - pa.bi[layer][idx];
        g_bI[layer][idx] = pa.br[layer][idx] + pa.bi[layer][idx];
    }
}

// ============================================================================
// merged split: 3 tensors in one launch (grid.z = q/k/v)
// fp32 (xr, xi) -> single fp16 r, i, s=r+i
// ============================================================================
struct alignas(8) HF4 { __half v[4]; };
struct SplitArgs { const float *xr[3], *xi[3]; };

__global__ void split_f(SplitArgs sa)
{
    const int z = blockIdx.z;
    size_t i4 = (size_t)(blockIdx.x * 256 + threadIdx.x) * 4;
    float4 vr = *(const float4*)(sa.xr[z] + i4);
    float4 vi = *(const float4*)(sa.xi[z] + i4);
    float ar[4] = {vr.x, vr.y, vr.z, vr.w};
    float ai[4] = {vi.x, vi.y, vi.z, vi.w};
    HF4 out[3];
#pragma unroll
    for (int j = 0; j < 4; j++) {
        out[0].v[j] = __float2half(ar[j]);
        out[1].v[j] = __float2half(ai[j]);
        out[2].v[j] = __float2half(ar[j] + ai[j]);
    }
    __half* X = g_Xh[z][0];
#pragma unroll
    for (int v = 0; v < 3; v++)
        *(HF4*)(X + (size_t)v * VS + i4) = out[v];
}

// ============================================================================
// fp16x2 P-GEMM: P = A_v @ (W_hi + W_lo)^T
// mode 0: QKV (z = layer*3 + p), mode 1: o-layer (z = p)
// 256 threads (8 warps, 4x2 grid, warp tile 32x64), 2 CTAs/SM,
// 3-stage cp.async ring, single __syncthreads per stage.
// ============================================================================
__global__ void __launch_bounds__(256, 2)
gemm_f(int mode)
{
    const int z = blockIdx.z;
    const __half *Ah_g, *Bhi_g, *Blo_g;
    float* Pout;
    if (mode == 0) {
        int layer = z / 3, p = z - 3 * layer;
        Ah_g  = g_Xh[layer][p];
        Bhi_g = g_Wf[layer][2 * p];
        Blo_g = g_Wf[layer][2 * p + 1];
        Pout  = g_P[z];
    } else {
        Ah_g  = g_Ao[z];
        Bhi_g = g_Wf[3][2 * z];
        Blo_g = g_Wf[3][2 * z + 1];
        Pout  = g_Po[z];
    }

    extern __shared__ char smem[];
    const int tid = threadIdx.x;
    const int wid = tid >> 5, lane = tid & 31;
    const int wm = wid >> 1, wn = wid & 1;        // 4 x 2 warps, tile 32 x 64
    const int r = lane >> 2, c = lane & 3;
    const int bm = blockIdx.x * BM, bn = blockIdx.y * BN;

    const uint32_t sb = (uint32_t)__cvta_generic_to_shared(smem);

    const int arow = (lane & 7) + ((lane >> 3) & 1) * 8;
    const int akof = ((lane >> 4) & 1) * 16;
    const uint32_t a_off = (uint32_t)((wm * 32 + arow) * ROWB + akof);
    const int brow = (lane & 7) + ((lane >> 4) & 1) * 8;
    const int bkof = ((lane >> 3) & 1) * 16;
    const uint32_t b_off = (uint32_t)((wn * 64 + brow) * ROWB + bkof);

    float acc[2][8][4];
#pragma unroll
    for (int mi = 0; mi < 2; mi++)
#pragma unroll
        for (int nj = 0; nj < 8; nj++)
#pragma unroll
            for (int e = 0; e < 4; e++) acc[mi][nj][e] = 0.f;

    // loader: A 512 chunks + Bhi 512 + Blo 512, 2 per thread each
    auto load_stage = [&](int slot, int kt) {
        uint32_t base = sb + slot * STAGE_F;
#pragma unroll
        for (int i = 0; i < 2; i++) {
            int j = tid + i * 256;
            int row = j >> 2, ch = j & 3;
            size_t goA = (size_t)(bm + row) * K512 + kt + ch * 8;
            size_t goB = (size_t)(bn + row) * K512 + kt + ch * 8;
            CP_ASYNC16(base + ST_FA  + row * ROWB + ch * 16, Ah_g + goA);
            CP_ASYNC16(base + ST_FBH + row * ROWB + ch * 16, Bhi_g + goB);
            CP_ASYNC16(base + ST_FBL + row * ROWB + ch * 16, Blo_g + goB);
        }
        CP_COMMIT();
    };

    // prologue: stages 0 and 1 in flight
    load_stage(0, 0);
    load_stage(1, BK);

    int slot = 0, next_slot = 2;
    for (int s = 0; s < KSTEPS; s++) {
        CP_WAIT(1);               // stage s complete (s+1 still in flight)
        __syncthreads();          // visibility + fences reuse of slot (s-1)

        if (s + 2 < KSTEPS) {
            load_stage(next_slot, (s + 2) * BK);
        }

        const uint32_t stb = sb + slot * STAGE_F;
#pragma unroll
        for (int kk = 0; kk < 2; kk++) {
            const uint32_t kb = stb + kk * 32;
            uint32_t ah[2][4];
#pragma unroll
            for (int mi = 0; mi < 2; mi++)
                LDSM_X4(ah[mi][0], ah[mi][1], ah[mi][2], ah[mi][3],
                        kb + ST_FA + a_off + mi * (16 * ROWB));
#pragma unroll
            for (int g = 0; g < 4; g++) {
                uint32_t bh[4], bl[4];
                LDSM_X4(bh[0], bh[1], bh[2], bh[3], kb + ST_FBH + b_off + g * (16 * ROWB));
                LDSM_X4(bl[0], bl[1], bl[2], bl[3], kb + ST_FBL + b_off + g * (16 * ROWB));
#pragma unroll
                for (int mi = 0; mi < 2; mi++) {
                    mma_f16(acc[mi][2 * g + 0], ah[mi], bh[0], bh[1]);
                    mma_f16(acc[mi][2 * g + 0], ah[mi], bl[0], bl[1]);
                    mma_f16(acc[mi][2 * g + 1], ah[mi], bh[2], bh[3]);
                    mma_f16(acc[mi][2 * g + 1], ah[mi], bl[2], bl[3]);
                }
            }
        }

        slot = (slot == NSTG - 1) ? 0 : slot + 1;
        next_slot = (next_slot == NSTG - 1) ? 0 : next_slot + 1;
    }

#pragma unroll
    for (int mi = 0; mi < 2; mi++)
#pragma unroll
        for (int nj = 0; nj < 8; nj++) {
            int ncol = bn + wn * 64 + nj * 8 + 2 * c;
            int row0 = bm + wm * 32 + mi * 16 + r;
#pragma unroll
            for (int hrow = 0; hrow < 2; hrow++) {
                float2 o = make_float2(acc[mi][nj][2 * hrow + 0], acc[mi][nj][2 * hrow + 1]);
                *(float2*)&Pout[(size_t)(row0 + 8 * hrow) * K512 + ncol] = o;
            }
        }
}

// ============================================================================
// channel attention with fused Gauss combine of Q/K/V (reads g_P fp32),
// writes o-GEMM input splits g_Ao (fp16 r,i,s)
// ============================================================================
__global__ void attn_kernel()
{
    __shared__ float sm[6][8][68];
    __shared__ float ssr[8][9], ssi[8][9];

    const int t = blockIdx.x, h = blockIdx.y, b = blockIdx.z;
    const int tid = threadIdx.x;

    {
        int cch = tid >> 4, d4 = (tid & 15) << 2;
        size_t m = ((size_t)(b * 8 + cch) * 512 + t);
        size_t off = m * K512 + h * 64 + d4;
        int col = h * 64 + d4;

#pragma unroll
        for (int layer = 0; layer < 3; layer++) {
            float4 p1 = *(const float4*)&g_P[layer * 3 + 0][off];
            float4 p2 = *(const float4*)&g_P[layer * 3 + 1][off];
            float4 p3 = *(const float4*)&g_P[layer * 3 + 2][off];
            float4 br = *(const float4*)&g_bR[layer][col];
            float4 bi = *(const float4*)&g_bI[layer][col];
            float4 yr, yi;
            yr.x = p1.x - p2.x + br.x;  yi.x = p3.x - p1.x - p2.x + bi.x;
            yr.y = p1.y - p2.y + br.y;  yi.y = p3.y - p1.y - p2.y + bi.y;
            yr.z = p1.z - p2.z + br.z;  yi.z = p3.z - p1.z - p2.z + bi.z;
            yr.w = p1.w - p2.w + br.w;  yi.w = p3.w - p1.w - p2.w + bi.w;
            if (layer == 2) {
                yr.x = yr.x >= 0.f ? yr.x : 0.01f * yr.x;
                yr.y = yr.y >= 0.f ? yr.y : 0.01f * yr.y;
                yr.z = yr.z >= 0.f ? yr.z : 0.01f * yr.z;
                yr.w = yr.w >= 0.f ? yr.w : 0.01f * yr.w;
                yi.x = yi.x >= 0.f ? yi.x : 0.01f * yi.x;
                yi.y = yi.y >= 0.f ? yi.y : 0.01f * yi.y;
                yi.z = yi.z >= 0.f ? yi.z : 0.01f * yi.z;
                yi.w = yi.w >= 0.f ? yi.w : 0.01f * yi.w;
            }
            *(float4*)&sm[2 * layer + 0][cch][d4] = yr;
            *(float4*)&sm[2 * layer + 1][cch][d4] = yi;
        }
    }
    __syncthreads();

    if (tid < 64) {
        int cc = tid >> 3, e = tid & 7;
        float ar = 0.f, ai = 0.f;
#pragma unroll 8
        for (int d = 0; d < 64; d++) {
            float qr = sm[0][cc][d], qi = sm[1][cc][d];
            float kr = sm[2][e][d],  ki = sm[3][e][d];
            ar = fmaf(qr, kr, fmaf(qi, ki, ar));
            ai = fmaf(qr, ki, fmaf(-qi, kr, ai));
        }
        ssr[cc][e] = ar * 0.125f;
        ssi[cc][e] = ai * 0.125f;
    }
    __syncthreads();

#pragma unroll
    for (int i = 0; i < 4; i++) {
        int idx = tid + i * 128;
        int cc = idx >> 6, d = idx & 63;
        float xr = 0.f, xi = 0.f;
#pragma unroll
        for (int e = 0; e < 8; e++) {
            float sr_ = ssr[cc][e], si_ = ssi[cc][e];
            float vr = sm[4][e][d], vi = sm[5][e][d];
            xr = fmaf(sr_, vr, fmaf(-si_, vi, xr));
            xi = fmaf(si_, vr, fmaf(sr_, vi, xi));
        }
        xr = xr >= 0.f ? xr : 0.01f * xr;
        xi = xi >= 0.f ? xi : 0.01f * xi;
        size_t mrow = (size_t)(b * 8 + cc) * 512 + t;
        size_t o = mrow * K512 + h * 64 + d;
        g_Ao[0][o] = __float2half(xr);
        g_Ao[1][o] = __float2half(xi);
        g_Ao[2][o] = __float2half(xr + xi);
    }
}

// ============================================================================
// o-layer Gauss combine: d_out = [Yr | Yi] from g_Po + biases
// ============================================================================
__global__ void combine_out(float* __restrict__ out)
{
    size_t i4 = (size_t)(blockIdx.x * 256 + threadIdx.x) * 4;
    int col = (int)(i4 & 511);
    float4 p1 = *(const float4*)&g_Po[0][i4];
    float4 p2 = *(const float4*)&g_Po[1][i4];
    float4 p3 = *(const float4*)&g_Po[2][i4];
    float4 br = *(const float4*)&g_bR[3][col];
    float4 bi = *(const float4*)&g_bI[3][col];
    float4 yr, yi;
    yr.x = p1.x - p2.x + br.x;  yi.x = p3.x - p1.x - p2.x + bi.x;
    yr.y = p1.y - p2.y + br.y;  yi.y = p3.y - p1.y - p2.y + bi.y;
    yr.z = p1.z - p2.z + br.z;  yi.z = p3.z - p1.z - p2.z + bi.z;
    yr.w = p1.w - p2.w + br.w;  yi.w = p3.w - p1.w - p2.w + bi.w;
    *(float4*)&out[i4] = yr;
    *(float4*)&out[(size_t)Mrows * K512 + i4] = yi;
}

// ============================================================================
// host side
// ============================================================================
extern "C" void kernel_launch(void* const* d_in, const int* in_sizes, int n_in,
                              void* d_out, int out_size)
{
    const float* in[22];
    for (int i = 0; i < 22; i++) in[i] = (const float*)d_in[i];

    cudaFuncSetAttribute(gemm_f, cudaFuncAttributeMaxDynamicSharedMemorySize, SMEM_F);

    // weights: 6=Wq_r 7=bq_r 8=Wq_i 9=bq_i | 10..13 k | 14..17 v | 18..21 o
    PackArgs pa;
    for (int l = 0; l < 4; l++) {
        pa.Wr[l] = in[6 + 4 * l];
        pa.br[l] = in[7 + 4 * l];
        pa.Wi[l] = in[8 + 4 * l];
        pa.bi[l] = in[9 + 4 * l];
    }
    pack_f<<<dim3(1024, 1, 4), 256>>>(pa);

    // input splits (q, k, v) -> fp16 r,i,s (merged launch)
    SplitArgs sa;
    sa.xr[0] = in[0]; sa.xi[0] = in[1];
    sa.xr[1] = in[2]; sa.xi[1] = in[3];
    sa.xr[2] = in[4]; sa.xi[2] = in[5];
    split_f<<<dim3(8192, 1, 3), 256>>>(sa);

    // 9 QKV P-GEMMs (fp16x2) in one launch
    gemm_f<<<dim3(Mrows / BM, K512 / BN, 9), 256, SMEM_F>>>(0);

    // attention (fused QKV Gauss combine)
    attn_kernel<<<dim3(512, 8, 4), 128>>>();

    // 3 o-layer P-GEMMs (fp16x2), then combine into d_out
    gemm_f<<<dim3(Mrows / BM, K512 / BN, 3), 256, SMEM_F>>>(1);
    combine_out<<<8192, 256>>>((float*)d_out);
}